// round 12
// baseline (speedup 1.0000x reference)
#include <cuda_runtime.h>

#define BB 2
#define SS 1024
#define DD 128
#define NCHUNK 16          // k chunks of 64

// Scratch (device globals; allocation-free per harness rules)
__device__ float g_Q[BB*SS*DD];
__device__ float g_K[BB*SS*DD];
__device__ float g_V[BB*SS*DD];
__device__ float g_sQ[BB*SS];                 // row sums of Q
__device__ float g_sK[BB*SS];                 // row sums of K
__device__ float g_part[NCHUNK][BB*SS*DD];    // split-K partials ((P-1) weighted)
__device__ float g_rsum[NCHUNK][BB*SS];       // split-K partial row sums of exp
__device__ float g_vseg[BB*16*DD];            // per-64-row segment sums of V
__device__ float g_vtot[BB*DD];               // total V row-sum per batch

// packed f32x2 helpers (sm_100+): 2 fp32 per fma-pipe instruction
__device__ __forceinline__ unsigned long long f32x2_add(unsigned long long a,
                                                        unsigned long long b)
{
    unsigned long long r;
    asm("add.rn.f32x2 %0, %1, %2;" : "=l"(r) : "l"(a), "l"(b));
    return r;
}
__device__ __forceinline__ float f32x2_hsum(unsigned long long a)
{
    float2 f = *(float2*)&a;
    return f.x + f.y;
}

// ---------------------------------------------------------------------------
// K1: Q/K/V projection + row-sum epilogue for Q,K.  (R11-proven)
// ---------------------------------------------------------------------------
__global__ __launch_bounds__(256) void qkv_kernel(
    const float* __restrict__ x,
    const float* __restrict__ Wq, const float* __restrict__ bq,
    const float* __restrict__ Wk, const float* __restrict__ bk,
    const float* __restrict__ Wv, const float* __restrict__ bv)
{
    __shared__ float xs[32*68];
    __shared__ float ws[128*68];
    const int t  = threadIdx.x;
    const int tx = t & 15;          // e = tx + 16*j
    const int ty = t >> 4;          // rows ty, ty+16
    const int mat = blockIdx.y;
    const int rowbase = blockIdx.x * 32;

    const float* W    = (mat == 0) ? Wq : (mat == 1) ? Wk : Wv;
    const float* bias = (mat == 0) ? bq : (mat == 1) ? bk : bv;

    float acc[2][8];
    #pragma unroll
    for (int i = 0; i < 2; i++)
        #pragma unroll
        for (int j = 0; j < 8; j++) acc[i][j] = 0.f;

    for (int dc = 0; dc < DD; dc += 64) {
        __syncthreads();
        #pragma unroll
        for (int i = 0; i < 8; i++) {
            int lin = t + i*256;
            int e = lin >> 4, c4 = lin & 15;
            *(float4*)(ws + e*68 + c4*4) = *(const float4*)(W + e*DD + dc + c4*4);
        }
        #pragma unroll
        for (int i = 0; i < 2; i++) {
            int lin = t + i*256;
            int r = lin >> 4, c4 = lin & 15;
            *(float4*)(xs + r*68 + c4*4) = *(const float4*)(x + (rowbase + r)*DD + dc + c4*4);
        }
        __syncthreads();
        #pragma unroll
        for (int d4 = 0; d4 < 16; d4++) {
            float4 x0 = *(const float4*)(xs + ty*68 + d4*4);
            float4 x1 = *(const float4*)(xs + (ty+16)*68 + d4*4);
            #pragma unroll
            for (int j = 0; j < 8; j++) {
                float4 w = *(const float4*)(ws + (tx + 16*j)*68 + d4*4);
                acc[0][j] += x0.x*w.x; acc[0][j] += x0.y*w.y;
                acc[0][j] += x0.z*w.z; acc[0][j] += x0.w*w.w;
                acc[1][j] += x1.x*w.x; acc[1][j] += x1.y*w.y;
                acc[1][j] += x1.z*w.z; acc[1][j] += x1.w*w.w;
            }
        }
    }

    float* out = (mat == 0) ? g_Q : (mat == 1) ? g_K : g_V;
    float rsum[2] = {0.f, 0.f};
    #pragma unroll
    for (int i = 0; i < 2; i++) {
        int r = rowbase + ty + 16*i;
        #pragma unroll
        for (int j = 0; j < 8; j++) {
            int e = tx + 16*j;
            float v = acc[i][j] + bias[e];
            if (mat < 2) v = 1.f / (1.f + __expf(-v));
            rsum[i] += v;
            out[r*DD + e] = v;
        }
    }
    if (mat < 2) {
        #pragma unroll
        for (int o = 1; o < 16; o <<= 1) {
            rsum[0] += __shfl_xor_sync(0xffffffffu, rsum[0], o);
            rsum[1] += __shfl_xor_sync(0xffffffffu, rsum[1], o);
        }
        if (tx == 0) {
            float* dst = (mat == 0) ? g_sQ : g_sK;
            dst[rowbase + ty]      = rsum[0];
            dst[rowbase + ty + 16] = rsum[1];
        }
    }
}

// ---------------------------------------------------------------------------
// V segment sums, then batch totals.
// ---------------------------------------------------------------------------
__global__ __launch_bounds__(128) void vseg_kernel()
{
    int b = blockIdx.x, s = blockIdx.y, d = threadIdx.x;
    const float* Vb = g_V + b*SS*DD;
    float a = 0.f;
    #pragma unroll 8
    for (int r = 0; r < 64; r++) a += Vb[(s*64 + r)*DD + d];
    g_vseg[(b*16 + s)*DD + d] = a;
}

__global__ __launch_bounds__(128) void vtot_kernel()
{
    int b = blockIdx.x, d = threadIdx.x;
    float a = 0.f;
    #pragma unroll
    for (int s = 0; s < 16; s++) a += g_vseg[(b*16 + s)*DD + d];
    g_vtot[b*DD + d] = a;
}

// ---------------------------------------------------------------------------
// Triangular chunk base: B(qi) = qi + floor((qi-1)^2/4), B(0) = 0.
// ---------------------------------------------------------------------------
__device__ __forceinline__ int tri_base(int qi)
{
    return (qi == 0) ? 0 : qi + ((qi - 1)*(qi - 1)) / 4;
}

// ---------------------------------------------------------------------------
// Fused flash-style kernel.  Score inner loop rewritten with packed f32x2:
// ks holds -K; diff via add.rn.f32x2 (fma pipe, 2 elems/instr), abs via
// 64-bit AND (alu pipe), accumulate via add.rn.f32x2.  fma-pipe ops per
// element drop 2 -> 1.  DYNAMIC smem (56KB).  grid (512, B), block 256.
// ---------------------------------------------------------------------------
#define QS_OFF 0
#define KS_OFF (32*132)
#define VS_OFF (2*32*132)
#define SS_OFF (3*32*132)
#define FUSED_SMEM_BYTES ((3*32*132 + 32*36) * 4)

__global__ __launch_bounds__(256, 4) void fused_kernel(const int* __restrict__ maskflag)
{
    const int causal = (maskflag[0] != 0);
    const int n = blockIdx.x;
    int qi, kc;
    if (causal) {
        if (n >= 272) return;
        qi = (int)(2.f * sqrtf((float)n + 1.f)) - 2;
        if (qi < 0) qi = 0;
        if (qi > 31) qi = 31;
        while (qi < 31 && tri_base(qi + 1) <= n) qi++;
        while (qi > 0  && tri_base(qi) > n)      qi--;
        kc = n - tri_base(qi);
    } else {
        qi = n >> 4;
        kc = n & 15;
    }
    const int qt = qi * 32;

    extern __shared__ float smem[];
    float* qs = smem + QS_OFF;
    float* ks = smem + KS_OFF;   // holds NEGATED K
    float* vs = smem + VS_OFF;
    float* ss = smem + SS_OFF;

    const int t  = threadIdx.x;
    const int tx = t & 15;         // score: k = k0 + tx, +16
    const int ty = t >> 4;         // score: q = qt + ty, +16
    const int tx2 = t & 31;        // pv: d = tx2*4
    const int ty2 = t >> 5;        // pv: q = ty2 + 8i
    const int b  = blockIdx.y;

    const float* Qb = g_Q + b*SS*DD;
    const float* Kb = g_K + b*SS*DD;
    const float* Vb = g_V + b*SS*DD;

    #pragma unroll
    for (int i = 0; i < 4; i++) {
        int lin = t + i*256;
        int r = lin >> 5, c = (lin & 31) * 4;
        *(float4*)(qs + r*132 + c) = *(const float4*)(Qb + (qt + r)*DD + c);
    }
    const float sQ0 = g_sQ[b*SS + qt + ty];
    const float sQ1 = g_sQ[b*SS + qt + ty + 16];

    float4 oacc[4];
    #pragma unroll
    for (int i = 0; i < 4; i++) oacc[i] = make_float4(0.f,0.f,0.f,0.f);
    float rs0 = 0.f, rs1 = 0.f;

    #pragma unroll
    for (int s = 0; s < 2; s++) {
        const int k0 = kc*64 + s*32;

        __syncthreads();
        // async V tile prefetch (lands before PV; overlapped with score)
        #pragma unroll
        for (int i = 0; i < 4; i++) {
            int lin = t + i*256;
            int r = lin >> 5, c = (lin & 31) * 4;
            unsigned dst = (unsigned)__cvta_generic_to_shared(vs + r*132 + c);
            const float* src = Vb + (k0 + r)*DD + c;
            asm volatile("cp.async.cg.shared.global [%0], [%1], 16;\n"
                         :: "r"(dst), "l"(src) : "memory");
        }
        asm volatile("cp.async.commit_group;\n" ::: "memory");
        // K tile, sign-flipped (ks = -K) so diffs are pure packed adds
        #pragma unroll
        for (int i = 0; i < 4; i++) {
            int lin = t + i*256;
            int r = lin >> 5, c = (lin & 31) * 4;
            uint4 kv = *(const uint4*)(Kb + (k0 + r)*DD + c);
            kv.x ^= 0x80000000u; kv.y ^= 0x80000000u;
            kv.z ^= 0x80000000u; kv.w ^= 0x80000000u;
            *(uint4*)(ks + r*132 + c) = kv;
        }
        __syncthreads();

        // --- score: A = sum_d |q - k|, packed f32x2 ---
        unsigned long long a00 = 0ull, a01 = 0ull, a10 = 0ull, a11 = 0ull;
        #pragma unroll 8
        for (int dq = 0; dq < 32; dq++) {
            ulonglong2 q0 = *(const ulonglong2*)(qs + ty*132 + dq*4);
            ulonglong2 q1 = *(const ulonglong2*)(qs + (ty+16)*132 + dq*4);
            ulonglong2 n0 = *(const ulonglong2*)(ks + tx*132 + dq*4);
            ulonglong2 n1 = *(const ulonglong2*)(ks + (tx+16)*132 + dq*4);
            const unsigned long long M = 0x7fffffff7fffffffull;
            a00 = f32x2_add(a00, f32x2_add(q0.x, n0.x) & M);
            a00 = f32x2_add(a00, f32x2_add(q0.y, n0.y) & M);
            a01 = f32x2_add(a01, f32x2_add(q0.x, n1.x) & M);
            a01 = f32x2_add(a01, f32x2_add(q0.y, n1.y) & M);
            a10 = f32x2_add(a10, f32x2_add(q1.x, n0.x) & M);
            a10 = f32x2_add(a10, f32x2_add(q1.y, n0.y) & M);
            a11 = f32x2_add(a11, f32x2_add(q1.x, n1.x) & M);
            a11 = f32x2_add(a11, f32x2_add(q1.y, n1.y) & M);
        }
        float A00 = f32x2_hsum(a00);
        float A01 = f32x2_hsum(a01);
        float A10 = f32x2_hsum(a10);
        float A11 = f32x2_hsum(a11);

        const float sK0 = g_sK[b*SS + k0 + tx];
        const float sK1 = g_sK[b*SS + k0 + tx + 16];

        float e00 = __expf(10.f - (sQ0 - sK0 + A00)*(10.f/256.f));
        float e01 = __expf(10.f - (sQ0 - sK1 + A01)*(10.f/256.f));
        float e10 = __expf(10.f - (sQ1 - sK0 + A10)*(10.f/256.f));
        float e11 = __expf(10.f - (sQ1 - sK1 + A11)*(10.f/256.f));
        if (causal) {
            int q0g = qt + ty, q1g = qt + ty + 16;
            int k0g = k0 + tx, k1g = k0 + tx + 16;
            if (k0g > q0g) e00 = 0.f;
            if (k1g > q0g) e01 = 0.f;
            if (k0g > q1g) e10 = 0.f;
            if (k1g > q1g) e11 = 0.f;
        }
        float l0 = e00 + e01, l1 = e10 + e11;
        #pragma unroll
        for (int o = 1; o < 16; o <<= 1) {
            l0 += __shfl_xor_sync(0xffffffffu, l0, o);
            l1 += __shfl_xor_sync(0xffffffffu, l1, o);
        }
        if (tx == 0) { rs0 += l0; rs1 += l1; }

        ss[ty*36 + tx]           = (e00 == 0.f) ? 0.f : e00 - 1.f;
        ss[ty*36 + tx + 16]      = (e01 == 0.f) ? 0.f : e01 - 1.f;
        ss[(ty+16)*36 + tx]      = (e10 == 0.f) ? 0.f : e10 - 1.f;
        ss[(ty+16)*36 + tx + 16] = (e11 == 0.f) ? 0.f : e11 - 1.f;

        asm volatile("cp.async.wait_group 0;\n" ::: "memory");
        __syncthreads();

        // --- PV accumulate (V from smem) ---
        #pragma unroll 2
        for (int kq = 0; kq < 8; kq++) {
            float4 p0 = *(const float4*)(ss + (ty2    )*36 + kq*4);
            float4 p1 = *(const float4*)(ss + (ty2+ 8)*36 + kq*4);
            float4 p2 = *(const float4*)(ss + (ty2+16)*36 + kq*4);
            float4 p3 = *(const float4*)(ss + (ty2+24)*36 + kq*4);
            #pragma unroll
            for (int c = 0; c < 4; c++) {
                float4 v = *(const float4*)(vs + (kq*4 + c)*132 + tx2*4);
                float pf0 = (&p0.x)[c], pf1 = (&p1.x)[c];
                float pf2 = (&p2.x)[c], pf3 = (&p3.x)[c];
                oacc[0].x += pf0*v.x; oacc[0].y += pf0*v.y; oacc[0].z += pf0*v.z; oacc[0].w += pf0*v.w;
                oacc[1].x += pf1*v.x; oacc[1].y += pf1*v.y; oacc[1].z += pf1*v.z; oacc[1].w += pf1*v.w;
                oacc[2].x += pf2*v.x; oacc[2].y += pf2*v.y; oacc[2].z += pf2*v.z; oacc[2].w += pf2*v.w;
                oacc[3].x += pf3*v.x; oacc[3].y += pf3*v.y; oacc[3].z += pf3*v.z; oacc[3].w += pf3*v.w;
            }
        }
    }

    float* dst = g_part[kc] + ((b << 10) + qt)*DD;
    #pragma unroll
    for (int i = 0; i < 4; i++)
        *(float4*)(dst + (ty2 + 8*i)*DD + tx2*4) = oacc[i];
    if (tx == 0) {
        g_rsum[kc][(b << 10) + qt + ty]      = rs0;
        g_rsum[kc][(b << 10) + qt + ty + 16] = rs1;
    }
}

// ---------------------------------------------------------------------------
// Reduce: out = (sum of active chunk partials + Vtot) * rinv.
// ---------------------------------------------------------------------------
__global__ __launch_bounds__(128) void out_reduce_kernel(float* __restrict__ out,
                                                          const int* __restrict__ maskflag)
{
    const int causal = (maskflag[0] != 0);
    int idx4 = blockIdx.x * 128 + threadIdx.x;
    int base = idx4 * 4;
    int row  = base >> 7;              // b*SS + q  (shared by all 32 lanes)
    int q    = row & (SS-1);
    int b    = row >> 10;
    int doff = base & 127;
    int lane = threadIdx.x & 31;

    int nc = causal ? ((q >> 6) + 1) : NCHUNK;

    float rp = (lane < nc) ? g_rsum[lane][row] : 0.f;
    #pragma unroll
    for (int o = 16; o > 0; o >>= 1) rp += __shfl_xor_sync(0xffffffffu, rp, o);
    float denom = rp + (causal ? (float)(SS - 1 - q) : 0.f);
    float rv = 1.f / denom;

    float4 s = *(const float4*)(g_vtot + (b << 7) + doff);
    #pragma unroll 4
    for (int j = 0; j < nc; j++) {
        float4 p = *(const float4*)(&g_part[j][base]);
        s.x += p.x; s.y += p.y; s.z += p.z; s.w += p.w;
    }
    s.x *= rv; s.y *= rv; s.z *= rv; s.w *= rv;
    *(float4*)(out + base) = s;
}

// ---------------------------------------------------------------------------
extern "C" void kernel_launch(void* const* d_in, const int* in_sizes, int n_in,
                              void* d_out, int out_size)
{
    const float* x  = (const float*)d_in[0];
    const float* Wq = (const float*)d_in[1];
    const float* bq = (const float*)d_in[2];
    const float* Wk = (const float*)d_in[3];
    const float* bk = (const float*)d_in[4];
    const float* Wv = (const float*)d_in[5];
    const float* bv = (const float*)d_in[6];
    const int*  msk = (const int*)d_in[7];
    float* out = (float*)d_out;

    cudaFuncSetAttribute(fused_kernel,
                         cudaFuncAttributeMaxDynamicSharedMemorySize,
                         FUSED_SMEM_BYTES);

    qkv_kernel    <<<dim3(BB*SS/32, 3), 256>>>(x, Wq, bq, Wk, bk, Wv, bv);
    vseg_kernel   <<<dim3(BB, 16), 128>>>();
    vtot_kernel   <<<BB, 128>>>();
    fused_kernel  <<<dim3(512, BB), 256, FUSED_SMEM_BYTES>>>(msk);
    out_reduce_kernel<<<BB*SS*DD/512, 128>>>(out, msk);
}

// round 13
// speedup vs baseline: 1.1170x; 1.1170x over previous
#include <cuda_runtime.h>

#define BB 2
#define SS 1024
#define DD 128
#define NCHUNK 16          // k chunks of 64

// Scratch (device globals; allocation-free per harness rules)
__device__ float g_Q[BB*SS*DD];
__device__ float g_K[BB*SS*DD];
__device__ float g_V[BB*SS*DD];
__device__ float g_sQ[BB*SS];                 // row sums of Q
__device__ float g_sK[BB*SS];                 // row sums of K
__device__ float g_part[NCHUNK][BB*SS*DD];    // split-K partials ((P-1) weighted)
__device__ float g_rsum[NCHUNK][BB*SS];       // split-K partial row sums of exp
__device__ float g_vseg32[BB*32*DD];          // per-32-row segment sums of V (from qkv)
__device__ float g_vtot[BB*DD];               // total V row-sum per batch (from fused tail)

// ---------------------------------------------------------------------------
// K1: Q/K/V projection + row-sum epilogue for Q,K + V column-segment sums.
// 32-row tile, float4 smem.  grid (64, 3), block 256.
// ---------------------------------------------------------------------------
__global__ __launch_bounds__(256) void qkv_kernel(
    const float* __restrict__ x,
    const float* __restrict__ Wq, const float* __restrict__ bq,
    const float* __restrict__ Wk, const float* __restrict__ bk,
    const float* __restrict__ Wv, const float* __restrict__ bv)
{
    __shared__ float xs[32*68];
    __shared__ float ws[128*68];
    const int t  = threadIdx.x;
    const int tx = t & 15;          // e = tx + 16*j
    const int ty = t >> 4;          // rows ty, ty+16
    const int mat = blockIdx.y;
    const int rowbase = blockIdx.x * 32;

    const float* W    = (mat == 0) ? Wq : (mat == 1) ? Wk : Wv;
    const float* bias = (mat == 0) ? bq : (mat == 1) ? bk : bv;

    float acc[2][8];
    #pragma unroll
    for (int i = 0; i < 2; i++)
        #pragma unroll
        for (int j = 0; j < 8; j++) acc[i][j] = 0.f;

    for (int dc = 0; dc < DD; dc += 64) {
        __syncthreads();
        #pragma unroll
        for (int i = 0; i < 8; i++) {
            int lin = t + i*256;
            int e = lin >> 4, c4 = lin & 15;
            *(float4*)(ws + e*68 + c4*4) = *(const float4*)(W + e*DD + dc + c4*4);
        }
        #pragma unroll
        for (int i = 0; i < 2; i++) {
            int lin = t + i*256;
            int r = lin >> 4, c4 = lin & 15;
            *(float4*)(xs + r*68 + c4*4) = *(const float4*)(x + (rowbase + r)*DD + dc + c4*4);
        }
        __syncthreads();
        #pragma unroll
        for (int d4 = 0; d4 < 16; d4++) {
            float4 x0 = *(const float4*)(xs + ty*68 + d4*4);
            float4 x1 = *(const float4*)(xs + (ty+16)*68 + d4*4);
            #pragma unroll
            for (int j = 0; j < 8; j++) {
                float4 w = *(const float4*)(ws + (tx + 16*j)*68 + d4*4);
                acc[0][j] += x0.x*w.x; acc[0][j] += x0.y*w.y;
                acc[0][j] += x0.z*w.z; acc[0][j] += x0.w*w.w;
                acc[1][j] += x1.x*w.x; acc[1][j] += x1.y*w.y;
                acc[1][j] += x1.z*w.z; acc[1][j] += x1.w*w.w;
            }
        }
    }

    float* out = (mat == 0) ? g_Q : (mat == 1) ? g_K : g_V;
    float rsum[2] = {0.f, 0.f};
    float pairsum[8];
    #pragma unroll
    for (int j = 0; j < 8; j++) pairsum[j] = 0.f;

    #pragma unroll
    for (int i = 0; i < 2; i++) {
        int r = rowbase + ty + 16*i;
        #pragma unroll
        for (int j = 0; j < 8; j++) {
            int e = tx + 16*j;
            float v = acc[i][j] + bias[e];
            if (mat < 2) v = 1.f / (1.f + __expf(-v));
            rsum[i] += v;
            pairsum[j] += v;
            out[r*DD + e] = v;
        }
    }
    if (mat < 2) {
        #pragma unroll
        for (int o = 1; o < 16; o <<= 1) {
            rsum[0] += __shfl_xor_sync(0xffffffffu, rsum[0], o);
            rsum[1] += __shfl_xor_sync(0xffffffffu, rsum[1], o);
        }
        if (tx == 0) {
            float* dst = (mat == 0) ? g_sQ : g_sK;
            dst[rowbase + ty]      = rsum[0];
            dst[rowbase + ty + 16] = rsum[1];
        }
    } else {
        // V column sums of this 32-row tile -> g_vseg32[blockIdx.x][e]
        __syncthreads();                   // all ws reads complete
        float* vsum = ws;                  // reuse (needs 16*132 <= 128*68)
        #pragma unroll
        for (int j = 0; j < 8; j++)
            vsum[ty*132 + tx + 16*j] = pairsum[j];
        __syncthreads();
        if (t < 128) {
            float ssum = 0.f;
            #pragma unroll
            for (int r = 0; r < 16; r++) ssum += vsum[r*132 + t];
            g_vseg32[blockIdx.x * DD + t] = ssum;
        }
    }
}

// ---------------------------------------------------------------------------
// Triangular chunk base: B(qi) = qi + floor((qi-1)^2/4), B(0) = 0.
// ---------------------------------------------------------------------------
__device__ __forceinline__ int tri_base(int qi)
{
    return (qi == 0) ? 0 : qi + ((qi - 1)*(qi - 1)) / 4;
}

// ---------------------------------------------------------------------------
// Fused flash-style kernel (R11-exact score path).  One block = one ACTIVE
// (32-q tile, 64-k chunk).  DYNAMIC smem (56KB): qs | ks | vs | ss.
// cp.async V prefetch.  Tail block (x==512, y==0) computes g_vtot from
// g_vseg32 (replaces the vtot kernel).  grid (513, B), block 256.
// ---------------------------------------------------------------------------
#define QS_OFF 0
#define KS_OFF (32*132)
#define VS_OFF (2*32*132)
#define SS_OFF (3*32*132)
#define FUSED_SMEM_BYTES ((3*32*132 + 32*36) * 4)

__global__ __launch_bounds__(256) void fused_kernel(const int* __restrict__ maskflag)
{
    const int causal = (maskflag[0] != 0);
    const int n = blockIdx.x;
    const int b = blockIdx.y;

    if (n == 512) {                       // vtot tail block
        if (b == 0) {
            int bb = threadIdx.x >> 7, d = threadIdx.x & 127;
            float a = 0.f;
            #pragma unroll 8
            for (int s2 = 0; s2 < 32; s2++)
                a += g_vseg32[(bb*32 + s2)*DD + d];
            g_vtot[bb*DD + d] = a;
        }
        return;
    }

    int qi, kc;
    if (causal) {
        if (n >= 272) return;
        qi = (int)(2.f * sqrtf((float)n + 1.f)) - 2;
        if (qi < 0) qi = 0;
        if (qi > 31) qi = 31;
        while (qi < 31 && tri_base(qi + 1) <= n) qi++;
        while (qi > 0  && tri_base(qi) > n)      qi--;
        kc = n - tri_base(qi);
    } else {
        qi = n >> 4;
        kc = n & 15;
    }
    const int qt = qi * 32;

    extern __shared__ float smem[];
    float* qs = smem + QS_OFF;
    float* ks = smem + KS_OFF;
    float* vs = smem + VS_OFF;
    float* ss = smem + SS_OFF;

    const int t  = threadIdx.x;
    const int tx = t & 15;         // score: k = k0 + tx, +16
    const int ty = t >> 4;         // score: q = qt + ty, +16
    const int tx2 = t & 31;        // pv: d = tx2*4
    const int ty2 = t >> 5;        // pv: q = ty2 + 8i

    const float* Qb = g_Q + b*SS*DD;
    const float* Kb = g_K + b*SS*DD;
    const float* Vb = g_V + b*SS*DD;

    #pragma unroll
    for (int i = 0; i < 4; i++) {
        int lin = t + i*256;
        int r = lin >> 5, c = (lin & 31) * 4;
        *(float4*)(qs + r*132 + c) = *(const float4*)(Qb + (qt + r)*DD + c);
    }
    const float sQ0 = g_sQ[b*SS + qt + ty];
    const float sQ1 = g_sQ[b*SS + qt + ty + 16];

    float4 oacc[4];
    #pragma unroll
    for (int i = 0; i < 4; i++) oacc[i] = make_float4(0.f,0.f,0.f,0.f);
    float rs0 = 0.f, rs1 = 0.f;

    #pragma unroll
    for (int s = 0; s < 2; s++) {
        const int k0 = kc*64 + s*32;

        __syncthreads();
        // async V tile prefetch (lands before PV; overlapped with score)
        #pragma unroll
        for (int i = 0; i < 4; i++) {
            int lin = t + i*256;
            int r = lin >> 5, c = (lin & 31) * 4;
            unsigned dst = (unsigned)__cvta_generic_to_shared(vs + r*132 + c);
            const float* src = Vb + (k0 + r)*DD + c;
            asm volatile("cp.async.cg.shared.global [%0], [%1], 16;\n"
                         :: "r"(dst), "l"(src) : "memory");
        }
        asm volatile("cp.async.commit_group;\n" ::: "memory");
        // K tile (regular ld/st; covered by the next barrier)
        #pragma unroll
        for (int i = 0; i < 4; i++) {
            int lin = t + i*256;
            int r = lin >> 5, c = (lin & 31) * 4;
            *(float4*)(ks + r*132 + c) = *(const float4*)(Kb + (k0 + r)*DD + c);
        }
        __syncthreads();

        // --- score: A = sum_d |q - k| ---
        float a00 = 0.f, a01 = 0.f, a10 = 0.f, a11 = 0.f;
        #pragma unroll 8
        for (int dq = 0; dq < 32; dq++) {
            float4 q0 = *(const float4*)(qs + ty*132 + dq*4);
            float4 q1 = *(const float4*)(qs + (ty+16)*132 + dq*4);
            float4 k0v = *(const float4*)(ks + tx*132 + dq*4);
            float4 k1v = *(const float4*)(ks + (tx+16)*132 + dq*4);
            a00 += fabsf(q0.x-k0v.x); a00 += fabsf(q0.y-k0v.y);
            a00 += fabsf(q0.z-k0v.z); a00 += fabsf(q0.w-k0v.w);
            a01 += fabsf(q0.x-k1v.x); a01 += fabsf(q0.y-k1v.y);
            a01 += fabsf(q0.z-k1v.z); a01 += fabsf(q0.w-k1v.w);
            a10 += fabsf(q1.x-k0v.x); a10 += fabsf(q1.y-k0v.y);
            a10 += fabsf(q1.z-k0v.z); a10 += fabsf(q1.w-k0v.w);
            a11 += fabsf(q1.x-k1v.x); a11 += fabsf(q1.y-k1v.y);
            a11 += fabsf(q1.z-k1v.z); a11 += fabsf(q1.w-k1v.w);
        }
        const float sK0 = g_sK[b*SS + k0 + tx];
        const float sK1 = g_sK[b*SS + k0 + tx + 16];

        float e00 = __expf(10.f - (sQ0 - sK0 + a00)*(10.f/256.f));
        float e01 = __expf(10.f - (sQ0 - sK1 + a01)*(10.f/256.f));
        float e10 = __expf(10.f - (sQ1 - sK0 + a10)*(10.f/256.f));
        float e11 = __expf(10.f - (sQ1 - sK1 + a11)*(10.f/256.f));
        if (causal) {
            int q0g = qt + ty, q1g = qt + ty + 16;
            int k0g = k0 + tx, k1g = k0 + tx + 16;
            if (k0g > q0g) e00 = 0.f;
            if (k1g > q0g) e01 = 0.f;
            if (k0g > q1g) e10 = 0.f;
            if (k1g > q1g) e11 = 0.f;
        }
        float l0 = e00 + e01, l1 = e10 + e11;
        #pragma unroll
        for (int o = 1; o < 16; o <<= 1) {
            l0 += __shfl_xor_sync(0xffffffffu, l0, o);
            l1 += __shfl_xor_sync(0xffffffffu, l1, o);
        }
        if (tx == 0) { rs0 += l0; rs1 += l1; }

        ss[ty*36 + tx]           = (e00 == 0.f) ? 0.f : e00 - 1.f;
        ss[ty*36 + tx + 16]      = (e01 == 0.f) ? 0.f : e01 - 1.f;
        ss[(ty+16)*36 + tx]      = (e10 == 0.f) ? 0.f : e10 - 1.f;
        ss[(ty+16)*36 + tx + 16] = (e11 == 0.f) ? 0.f : e11 - 1.f;

        asm volatile("cp.async.wait_group 0;\n" ::: "memory");
        __syncthreads();

        // --- PV accumulate (V from smem) ---
        #pragma unroll 2
        for (int kq = 0; kq < 8; kq++) {
            float4 p0 = *(const float4*)(ss + (ty2    )*36 + kq*4);
            float4 p1 = *(const float4*)(ss + (ty2+ 8)*36 + kq*4);
            float4 p2 = *(const float4*)(ss + (ty2+16)*36 + kq*4);
            float4 p3 = *(const float4*)(ss + (ty2+24)*36 + kq*4);
            #pragma unroll
            for (int c = 0; c < 4; c++) {
                float4 v = *(const float4*)(vs + (kq*4 + c)*132 + tx2*4);
                float pf0 = (&p0.x)[c], pf1 = (&p1.x)[c];
                float pf2 = (&p2.x)[c], pf3 = (&p3.x)[c];
                oacc[0].x += pf0*v.x; oacc[0].y += pf0*v.y; oacc[0].z += pf0*v.z; oacc[0].w += pf0*v.w;
                oacc[1].x += pf1*v.x; oacc[1].y += pf1*v.y; oacc[1].z += pf1*v.z; oacc[1].w += pf1*v.w;
                oacc[2].x += pf2*v.x; oacc[2].y += pf2*v.y; oacc[2].z += pf2*v.z; oacc[2].w += pf2*v.w;
                oacc[3].x += pf3*v.x; oacc[3].y += pf3*v.y; oacc[3].z += pf3*v.z; oacc[3].w += pf3*v.w;
            }
        }
    }

    float* dst = g_part[kc] + ((b << 10) + qt)*DD;
    #pragma unroll
    for (int i = 0; i < 4; i++)
        *(float4*)(dst + (ty2 + 8*i)*DD + tx2*4) = oacc[i];
    if (tx == 0) {
        g_rsum[kc][(b << 10) + qt + ty]      = rs0;
        g_rsum[kc][(b << 10) + qt + ty + 16] = rs1;
    }
}

// ---------------------------------------------------------------------------
// Reduce: out = (sum of active chunk partials + Vtot) * rinv.
// ---------------------------------------------------------------------------
__global__ __launch_bounds__(128) void out_reduce_kernel(float* __restrict__ out,
                                                          const int* __restrict__ maskflag)
{
    const int causal = (maskflag[0] != 0);
    int idx4 = blockIdx.x * 128 + threadIdx.x;
    int base = idx4 * 4;
    int row  = base >> 7;              // b*SS + q  (shared by all 32 lanes)
    int q    = row & (SS-1);
    int b    = row >> 10;
    int doff = base & 127;
    int lane = threadIdx.x & 31;

    int nc = causal ? ((q >> 6) + 1) : NCHUNK;

    float rp = (lane < nc) ? g_rsum[lane][row] : 0.f;
    #pragma unroll
    for (int o = 16; o > 0; o >>= 1) rp += __shfl_xor_sync(0xffffffffu, rp, o);
    float denom = rp + (causal ? (float)(SS - 1 - q) : 0.f);
    float rv = 1.f / denom;

    float4 s = *(const float4*)(g_vtot + (b << 7) + doff);
    #pragma unroll 4
    for (int j = 0; j < nc; j++) {
        float4 p = *(const float4*)(&g_part[j][base]);
        s.x += p.x; s.y += p.y; s.z += p.z; s.w += p.w;
    }
    s.x *= rv; s.y *= rv; s.z *= rv; s.w *= rv;
    *(float4*)(out + base) = s;
}

// ---------------------------------------------------------------------------
extern "C" void kernel_launch(void* const* d_in, const int* in_sizes, int n_in,
                              void* d_out, int out_size)
{
    const float* x  = (const float*)d_in[0];
    const float* Wq = (const float*)d_in[1];
    const float* bq = (const float*)d_in[2];
    const float* Wk = (const float*)d_in[3];
    const float* bk = (const float*)d_in[4];
    const float* Wv = (const float*)d_in[5];
    const float* bv = (const float*)d_in[6];
    const int*  msk = (const int*)d_in[7];
    float* out = (float*)d_out;

    cudaFuncSetAttribute(fused_kernel,
                         cudaFuncAttributeMaxDynamicSharedMemorySize,
                         FUSED_SMEM_BYTES);

    qkv_kernel    <<<dim3(BB*SS/32, 3), 256>>>(x, Wq, bq, Wk, bk, Wv, bv);
    fused_kernel  <<<dim3(513, BB), 256, FUSED_SMEM_BYTES>>>(msk);
    out_reduce_kernel<<<BB*SS*DD/512, 128>>>(out, msk);
}

// round 14
// speedup vs baseline: 1.1799x; 1.0563x over previous
#include <cuda_runtime.h>

#define BB 2
#define SS 1024
#define DD 128
#define NCHUNK 16          // k chunks of 64

// Scratch (device globals; allocation-free per harness rules)
__device__ float g_Q[BB*SS*DD];
__device__ float g_K[BB*SS*DD];
__device__ float g_V[BB*SS*DD];
__device__ float g_sQp[2][BB*SS];             // per-e-half row-sum partials of Q
__device__ float g_sKp[2][BB*SS];             // per-e-half row-sum partials of K
__device__ float g_part[NCHUNK][BB*SS*DD];    // split-K partials ((P-1) weighted)
__device__ float g_rsum[NCHUNK][BB*SS];       // split-K partial row sums of exp
__device__ float g_vseg32[BB*32*DD];          // per-32-row segment sums of V (from qkv)
__device__ float g_vtot[BB*DD];               // total V row-sum per batch (from fused tail)

// ---------------------------------------------------------------------------
// K1: Q/K/V projection, e-split for occupancy.
// grid (64 row-tiles, 2 e-halves, 3 mats) = 384 blocks, block 256.
// Per block: 32 rows x 64 e, d in 2 chunks of 64.  smem 26KB.
// Epilogue: partial row sums (Q,K) / V column-segment sums (V).
// ---------------------------------------------------------------------------
__global__ __launch_bounds__(256) void qkv_kernel(
    const float* __restrict__ x,
    const float* __restrict__ Wq, const float* __restrict__ bq,
    const float* __restrict__ Wk, const float* __restrict__ bk,
    const float* __restrict__ Wv, const float* __restrict__ bv)
{
    __shared__ float xs[32*68];
    __shared__ float ws[64*68];
    const int t  = threadIdx.x;
    const int tx = t & 15;          // e = ebase + tx + 16*j, j<4
    const int ty = t >> 4;          // rows ty, ty+16
    const int ehalf = blockIdx.y;
    const int mat = blockIdx.z;
    const int rowbase = blockIdx.x * 32;
    const int ebase = ehalf * 64;

    const float* W    = (mat == 0) ? Wq : (mat == 1) ? Wk : Wv;
    const float* bias = (mat == 0) ? bq : (mat == 1) ? bk : bv;

    float acc[2][4];
    #pragma unroll
    for (int i = 0; i < 2; i++)
        #pragma unroll
        for (int j = 0; j < 4; j++) acc[i][j] = 0.f;

    for (int dc = 0; dc < DD; dc += 64) {
        __syncthreads();
        // W chunk [64 e][64 d]: 64*16 float4 / 256 = 4 each
        #pragma unroll
        for (int i = 0; i < 4; i++) {
            int lin = t + i*256;
            int e = lin >> 4, c4 = lin & 15;
            *(float4*)(ws + e*68 + c4*4) = *(const float4*)(W + (ebase + e)*DD + dc + c4*4);
        }
        // x chunk [32][64]: 2 each
        #pragma unroll
        for (int i = 0; i < 2; i++) {
            int lin = t + i*256;
            int r = lin >> 4, c4 = lin & 15;
            *(float4*)(xs + r*68 + c4*4) = *(const float4*)(x + (rowbase + r)*DD + dc + c4*4);
        }
        __syncthreads();
        #pragma unroll
        for (int d4 = 0; d4 < 16; d4++) {
            float4 x0 = *(const float4*)(xs + ty*68 + d4*4);
            float4 x1 = *(const float4*)(xs + (ty+16)*68 + d4*4);
            #pragma unroll
            for (int j = 0; j < 4; j++) {
                float4 w = *(const float4*)(ws + (tx + 16*j)*68 + d4*4);
                acc[0][j] += x0.x*w.x; acc[0][j] += x0.y*w.y;
                acc[0][j] += x0.z*w.z; acc[0][j] += x0.w*w.w;
                acc[1][j] += x1.x*w.x; acc[1][j] += x1.y*w.y;
                acc[1][j] += x1.z*w.z; acc[1][j] += x1.w*w.w;
            }
        }
    }

    float* out = (mat == 0) ? g_Q : (mat == 1) ? g_K : g_V;
    float rsum[2] = {0.f, 0.f};
    float pairsum[4] = {0.f, 0.f, 0.f, 0.f};

    #pragma unroll
    for (int i = 0; i < 2; i++) {
        int r = rowbase + ty + 16*i;
        #pragma unroll
        for (int j = 0; j < 4; j++) {
            int e = ebase + tx + 16*j;
            float v = acc[i][j] + bias[e];
            if (mat < 2) v = 1.f / (1.f + __expf(-v));
            rsum[i] += v;
            pairsum[j] += v;
            out[r*DD + e] = v;
        }
    }
    if (mat < 2) {
        #pragma unroll
        for (int o = 1; o < 16; o <<= 1) {
            rsum[0] += __shfl_xor_sync(0xffffffffu, rsum[0], o);
            rsum[1] += __shfl_xor_sync(0xffffffffu, rsum[1], o);
        }
        if (tx == 0) {
            float* dst = (mat == 0) ? g_sQp[ehalf] : g_sKp[ehalf];
            dst[rowbase + ty]      = rsum[0];
            dst[rowbase + ty + 16] = rsum[1];
        }
    } else {
        // V column sums (32 rows) for this block's 64 columns
        __syncthreads();                   // all ws/xs reads complete
        float* vsum = ws;                  // 16 x 64 (stride 68) fits in ws
        #pragma unroll
        for (int j = 0; j < 4; j++)
            vsum[ty*68 + tx + 16*j] = pairsum[j];
        __syncthreads();
        if (t < 64) {
            float ssum = 0.f;
            #pragma unroll
            for (int r = 0; r < 16; r++) ssum += vsum[r*68 + t];
            g_vseg32[blockIdx.x * DD + ebase + t] = ssum;
        }
    }
}

// ---------------------------------------------------------------------------
// Triangular chunk base: B(qi) = qi + floor((qi-1)^2/4), B(0) = 0.
// ---------------------------------------------------------------------------
__device__ __forceinline__ int tri_base(int qi)
{
    return (qi == 0) ? 0 : qi + ((qi - 1)*(qi - 1)) / 4;
}

// ---------------------------------------------------------------------------
// Fused flash-style kernel (R13-exact apart from split row-sum loads).
// Tail block (x==512, y==0) computes g_vtot.  grid (513, B), block 256.
// ---------------------------------------------------------------------------
#define QS_OFF 0
#define KS_OFF (32*132)
#define VS_OFF (2*32*132)
#define SS_OFF (3*32*132)
#define FUSED_SMEM_BYTES ((3*32*132 + 32*36) * 4)

__global__ __launch_bounds__(256) void fused_kernel(const int* __restrict__ maskflag)
{
    const int causal = (maskflag[0] != 0);
    const int n = blockIdx.x;
    const int b = blockIdx.y;

    if (n == 512) {                       // vtot tail block
        if (b == 0) {
            int bb = threadIdx.x >> 7, d = threadIdx.x & 127;
            float a = 0.f;
            #pragma unroll 8
            for (int s2 = 0; s2 < 32; s2++)
                a += g_vseg32[(bb*32 + s2)*DD + d];
            g_vtot[bb*DD + d] = a;
        }
        return;
    }

    int qi, kc;
    if (causal) {
        if (n >= 272) return;
        qi = (int)(2.f * sqrtf((float)n + 1.f)) - 2;
        if (qi < 0) qi = 0;
        if (qi > 31) qi = 31;
        while (qi < 31 && tri_base(qi + 1) <= n) qi++;
        while (qi > 0  && tri_base(qi) > n)      qi--;
        kc = n - tri_base(qi);
    } else {
        qi = n >> 4;
        kc = n & 15;
    }
    const int qt = qi * 32;

    extern __shared__ float smem[];
    float* qs = smem + QS_OFF;
    float* ks = smem + KS_OFF;
    float* vs = smem + VS_OFF;
    float* ss = smem + SS_OFF;

    const int t  = threadIdx.x;
    const int tx = t & 15;         // score: k = k0 + tx, +16
    const int ty = t >> 4;         // score: q = qt + ty, +16
    const int tx2 = t & 31;        // pv: d = tx2*4
    const int ty2 = t >> 5;        // pv: q = ty2 + 8i

    const float* Qb = g_Q + b*SS*DD;
    const float* Kb = g_K + b*SS*DD;
    const float* Vb = g_V + b*SS*DD;

    #pragma unroll
    for (int i = 0; i < 4; i++) {
        int lin = t + i*256;
        int r = lin >> 5, c = (lin & 31) * 4;
        *(float4*)(qs + r*132 + c) = *(const float4*)(Qb + (qt + r)*DD + c);
    }
    const float sQ0 = g_sQp[0][b*SS + qt + ty]      + g_sQp[1][b*SS + qt + ty];
    const float sQ1 = g_sQp[0][b*SS + qt + ty + 16] + g_sQp[1][b*SS + qt + ty + 16];

    float4 oacc[4];
    #pragma unroll
    for (int i = 0; i < 4; i++) oacc[i] = make_float4(0.f,0.f,0.f,0.f);
    float rs0 = 0.f, rs1 = 0.f;

    #pragma unroll
    for (int s = 0; s < 2; s++) {
        const int k0 = kc*64 + s*32;

        __syncthreads();
        // async V tile prefetch (lands before PV; overlapped with score)
        #pragma unroll
        for (int i = 0; i < 4; i++) {
            int lin = t + i*256;
            int r = lin >> 5, c = (lin & 31) * 4;
            unsigned dst = (unsigned)__cvta_generic_to_shared(vs + r*132 + c);
            const float* src = Vb + (k0 + r)*DD + c;
            asm volatile("cp.async.cg.shared.global [%0], [%1], 16;\n"
                         :: "r"(dst), "l"(src) : "memory");
        }
        asm volatile("cp.async.commit_group;\n" ::: "memory");
        // K tile (regular ld/st; covered by the next barrier)
        #pragma unroll
        for (int i = 0; i < 4; i++) {
            int lin = t + i*256;
            int r = lin >> 5, c = (lin & 31) * 4;
            *(float4*)(ks + r*132 + c) = *(const float4*)(Kb + (k0 + r)*DD + c);
        }
        __syncthreads();

        // --- score: A = sum_d |q - k| ---
        float a00 = 0.f, a01 = 0.f, a10 = 0.f, a11 = 0.f;
        #pragma unroll 8
        for (int dq = 0; dq < 32; dq++) {
            float4 q0 = *(const float4*)(qs + ty*132 + dq*4);
            float4 q1 = *(const float4*)(qs + (ty+16)*132 + dq*4);
            float4 k0v = *(const float4*)(ks + tx*132 + dq*4);
            float4 k1v = *(const float4*)(ks + (tx+16)*132 + dq*4);
            a00 += fabsf(q0.x-k0v.x); a00 += fabsf(q0.y-k0v.y);
            a00 += fabsf(q0.z-k0v.z); a00 += fabsf(q0.w-k0v.w);
            a01 += fabsf(q0.x-k1v.x); a01 += fabsf(q0.y-k1v.y);
            a01 += fabsf(q0.z-k1v.z); a01 += fabsf(q0.w-k1v.w);
            a10 += fabsf(q1.x-k0v.x); a10 += fabsf(q1.y-k0v.y);
            a10 += fabsf(q1.z-k0v.z); a10 += fabsf(q1.w-k0v.w);
            a11 += fabsf(q1.x-k1v.x); a11 += fabsf(q1.y-k1v.y);
            a11 += fabsf(q1.z-k1v.z); a11 += fabsf(q1.w-k1v.w);
        }
        const float sK0 = g_sKp[0][b*SS + k0 + tx]      + g_sKp[1][b*SS + k0 + tx];
        const float sK1 = g_sKp[0][b*SS + k0 + tx + 16] + g_sKp[1][b*SS + k0 + tx + 16];

        float e00 = __expf(10.f - (sQ0 - sK0 + a00)*(10.f/256.f));
        float e01 = __expf(10.f - (sQ0 - sK1 + a01)*(10.f/256.f));
        float e10 = __expf(10.f - (sQ1 - sK0 + a10)*(10.f/256.f));
        float e11 = __expf(10.f - (sQ1 - sK1 + a11)*(10.f/256.f));
        if (causal) {
            int q0g = qt + ty, q1g = qt + ty + 16;
            int k0g = k0 + tx, k1g = k0 + tx + 16;
            if (k0g > q0g) e00 = 0.f;
            if (k1g > q0g) e01 = 0.f;
            if (k0g > q1g) e10 = 0.f;
            if (k1g > q1g) e11 = 0.f;
        }
        float l0 = e00 + e01, l1 = e10 + e11;
        #pragma unroll
        for (int o = 1; o < 16; o <<= 1) {
            l0 += __shfl_xor_sync(0xffffffffu, l0, o);
            l1 += __shfl_xor_sync(0xffffffffu, l1, o);
        }
        if (tx == 0) { rs0 += l0; rs1 += l1; }

        ss[ty*36 + tx]           = (e00 == 0.f) ? 0.f : e00 - 1.f;
        ss[ty*36 + tx + 16]      = (e01 == 0.f) ? 0.f : e01 - 1.f;
        ss[(ty+16)*36 + tx]      = (e10 == 0.f) ? 0.f : e10 - 1.f;
        ss[(ty+16)*36 + tx + 16] = (e11 == 0.f) ? 0.f : e11 - 1.f;

        asm volatile("cp.async.wait_group 0;\n" ::: "memory");
        __syncthreads();

        // --- PV accumulate (V from smem) ---
        #pragma unroll 2
        for (int kq = 0; kq < 8; kq++) {
            float4 p0 = *(const float4*)(ss + (ty2    )*36 + kq*4);
            float4 p1 = *(const float4*)(ss + (ty2+ 8)*36 + kq*4);
            float4 p2 = *(const float4*)(ss + (ty2+16)*36 + kq*4);
            float4 p3 = *(const float4*)(ss + (ty2+24)*36 + kq*4);
            #pragma unroll
            for (int c = 0; c < 4; c++) {
                float4 v = *(const float4*)(vs + (kq*4 + c)*132 + tx2*4);
                float pf0 = (&p0.x)[c], pf1 = (&p1.x)[c];
                float pf2 = (&p2.x)[c], pf3 = (&p3.x)[c];
                oacc[0].x += pf0*v.x; oacc[0].y += pf0*v.y; oacc[0].z += pf0*v.z; oacc[0].w += pf0*v.w;
                oacc[1].x += pf1*v.x; oacc[1].y += pf1*v.y; oacc[1].z += pf1*v.z; oacc[1].w += pf1*v.w;
                oacc[2].x += pf2*v.x; oacc[2].y += pf2*v.y; oacc[2].z += pf2*v.z; oacc[2].w += pf2*v.w;
                oacc[3].x += pf3*v.x; oacc[3].y += pf3*v.y; oacc[3].z += pf3*v.z; oacc[3].w += pf3*v.w;
            }
        }
    }

    float* dst = g_part[kc] + ((b << 10) + qt)*DD;
    #pragma unroll
    for (int i = 0; i < 4; i++)
        *(float4*)(dst + (ty2 + 8*i)*DD + tx2*4) = oacc[i];
    if (tx == 0) {
        g_rsum[kc][(b << 10) + qt + ty]      = rs0;
        g_rsum[kc][(b << 10) + qt + ty + 16] = rs1;
    }
}

// ---------------------------------------------------------------------------
// Reduce: out = (sum of active chunk partials + Vtot) * rinv.
// ---------------------------------------------------------------------------
__global__ __launch_bounds__(128) void out_reduce_kernel(float* __restrict__ out,
                                                          const int* __restrict__ maskflag)
{
    const int causal = (maskflag[0] != 0);
    int idx4 = blockIdx.x * 128 + threadIdx.x;
    int base = idx4 * 4;
    int row  = base >> 7;              // b*SS + q  (shared by all 32 lanes)
    int q    = row & (SS-1);
    int b    = row >> 10;
    int doff = base & 127;
    int lane = threadIdx.x & 31;

    int nc = causal ? ((q >> 6) + 1) : NCHUNK;

    float rp = (lane < nc) ? g_rsum[lane][row] : 0.f;
    #pragma unroll
    for (int o = 16; o > 0; o >>= 1) rp += __shfl_xor_sync(0xffffffffu, rp, o);
    float denom = rp + (causal ? (float)(SS - 1 - q) : 0.f);
    float rv = 1.f / denom;

    float4 s = *(const float4*)(g_vtot + (b << 7) + doff);
    #pragma unroll 4
    for (int j = 0; j < nc; j++) {
        float4 p = *(const float4*)(&g_part[j][base]);
        s.x += p.x; s.y += p.y; s.z += p.z; s.w += p.w;
    }
    s.x *= rv; s.y *= rv; s.z *= rv; s.w *= rv;
    *(float4*)(out + base) = s;
}

// ---------------------------------------------------------------------------
extern "C" void kernel_launch(void* const* d_in, const int* in_sizes, int n_in,
                              void* d_out, int out_size)
{
    const float* x  = (const float*)d_in[0];
    const float* Wq = (const float*)d_in[1];
    const float* bq = (const float*)d_in[2];
    const float* Wk = (const float*)d_in[3];
    const float* bk = (const float*)d_in[4];
    const float* Wv = (const float*)d_in[5];
    const float* bv = (const float*)d_in[6];
    const int*  msk = (const int*)d_in[7];
    float* out = (float*)d_out;

    cudaFuncSetAttribute(fused_kernel,
                         cudaFuncAttributeMaxDynamicSharedMemorySize,
                         FUSED_SMEM_BYTES);

    qkv_kernel    <<<dim3(BB*SS/32, 2, 3), 256>>>(x, Wq, bq, Wk, bk, Wv, bv);
    fused_kernel  <<<dim3(513, BB), 256, FUSED_SMEM_BYTES>>>(msk);
    out_reduce_kernel<<<BB*SS*DD/512, 128>>>(out, msk);
}